// round 9
// baseline (speedup 1.0000x reference)
#include <cuda_runtime.h>
#include <cstdint>

#define BB 4
#define SEQ 2048
#define EMB 1024
#define NH 16
#define HD 64
#define MT (BB * SEQ)  // 8192 tokens

// Scratch (allocation-free rule: device globals)
__device__ float g_q[BB * NH * SEQ * HD];   // [b][h][s][d]
__device__ float g_k[BB * NH * SEQ * HD];
__device__ float g_v[BB * NH * SEQ * HD];
__device__ float g_ao[MT * EMB];            // attention out, [b][s][h*64+d] == [m][e]

// ---------------------------------------------------------------------------
// tf32 helpers (baseline PTX, works at .target sm_100)
// ---------------------------------------------------------------------------
__device__ __forceinline__ uint32_t f2tf32(float x) {
  uint32_t r;
  asm("cvt.rna.tf32.f32 %0, %1;" : "=r"(r) : "f"(x));
  return r;
}

__device__ __forceinline__ void split1(float v, uint32_t& h, uint32_t& l) {
  h = f2tf32(v);
  l = f2tf32(v - __uint_as_float(h));
}

__device__ __forceinline__ void mma_tf32(float* c, const uint32_t* a,
                                         const uint32_t* b) {
  asm volatile(
      "mma.sync.aligned.m16n8k8.row.col.f32.tf32.tf32.f32 "
      "{%0,%1,%2,%3}, {%4,%5,%6,%7}, {%8,%9}, {%0,%1,%2,%3};"
      : "+f"(c[0]), "+f"(c[1]), "+f"(c[2]), "+f"(c[3])
      : "r"(a[0]), "r"(a[1]), "r"(a[2]), "r"(a[3]), "r"(b[0]), "r"(b[1]));
}

// ---------------------------------------------------------------------------
// tf32 3x-split GEMM, double-buffered, interleaved (hi,lo) uint2 smem layout:
//   X2[row][k] = (hi, lo) of element (row, k0+k),  row stride 20 uint2
//   (40 words ≡ 8 mod 32 -> phase-wise conflict-free LDS.64 fragment loads)
// ONE __syncthreads per BK=16 chunk. CTA 128x128, 256 threads.
// NO min-CTA clause: ptxas free to use ~154 regs (R8 proved capping -> spills).
// MODE 0: A=query, scatter into g_q/g_k/g_v. MODE 1: A=g_ao, write out.
// ---------------------------------------------------------------------------
#define SP2 20                        // uint2 row stride
#define TILE_U2 (128 * SP2)           // one operand tile in uint2
#define GEMM_SMEM_BYTES (2 * 2 * TILE_U2 * 8)  // 2 bufs x {A,B} = 81920 B

template <int MODE>
__global__ __launch_bounds__(256) void gemm_mma_kernel(
    const float* __restrict__ A, const float* __restrict__ B,
    const float* __restrict__ bias, float* __restrict__ out) {
  extern __shared__ uint2 gsm[];  // [buf][A2 | B2]

  const int tid = threadIdx.x;
  const int lane = tid & 31;
  const int wid = tid >> 5;
  const int warp_m = wid & 1;        // 2 warps over M
  const int warp_n = wid >> 1;       // 4 warps over N
  const int m0 = blockIdx.y * 128;
  const int n0 = blockIdx.x * 128;

  const float* Asrc = (MODE == 0) ? A : g_ao;

  const int ldr = tid >> 2;          // rows 0..63 (+64 for second half)
  const int ldc = (tid & 3) * 4;     // 0,4,8,12

  const float* Ap0 = Asrc + (size_t)(m0 + ldr) * EMB + ldc;
  const float* Ap1 = Asrc + (size_t)(m0 + 64 + ldr) * EMB + ldc;
  const float* Bp0 = B + (size_t)(n0 + ldr) * EMB + ldc;
  const float* Bp1 = B + (size_t)(n0 + 64 + ldr) * EMB + ldc;

  float acc[4][4][4] = {};  // [mt][nt][reg]

  const int sa0 = ldr * SP2 + ldc;          // uint2 index, row ldr
  const int sa1 = (ldr + 64) * SP2 + ldc;   // row ldr+64

  float4 pa0 = *(const float4*)(Ap0);
  float4 pa1 = *(const float4*)(Ap1);
  float4 pb0 = *(const float4*)(Bp0);
  float4 pb1 = *(const float4*)(Bp1);

  // split+store one float4 as two uint4 {hi0,lo0,hi1,lo1} STS.128
#define SPLIT_STORE4(dst, idx, v)                                   \
  do {                                                              \
    uint4 u0, u1;                                                   \
    split1((v).x, u0.x, u0.y); split1((v).y, u0.z, u0.w);           \
    split1((v).z, u1.x, u1.y); split1((v).w, u1.z, u1.w);           \
    *(uint4*)&(dst)[idx] = u0;                                      \
    *(uint4*)&(dst)[(idx) + 2] = u1;                                \
  } while (0)

  // prologue: chunk 0 -> buffer 0
  {
    uint2* A2 = gsm;
    uint2* B2 = gsm + TILE_U2;
    SPLIT_STORE4(A2, sa0, pa0);
    SPLIT_STORE4(A2, sa1, pa1);
    SPLIT_STORE4(B2, sa0, pb0);
    SPLIT_STORE4(B2, sa1, pb1);
  }

  for (int c = 0; c < EMB / 16; ++c) {
    __syncthreads();  // stores of chunk c done; computes of chunk c-1 done

    const bool more = (c + 1 < EMB / 16);
    if (more) {
      const int off = (c + 1) * 16;
      pa0 = *(const float4*)(Ap0 + off);
      pa1 = *(const float4*)(Ap1 + off);
      pb0 = *(const float4*)(Bp0 + off);
      pb1 = *(const float4*)(Bp1 + off);
    }

    // compute chunk c from buffer c&1
    {
      const uint2* A2 = gsm + (c & 1) * (2 * TILE_U2);
      const uint2* B2 = A2 + TILE_U2;
#pragma unroll
      for (int kc = 0; kc < 2; ++kc) {
        const int kb = kc * 8 + (lane & 3);
        uint32_t ah[4][4], al[4][4];
#pragma unroll
        for (int mt = 0; mt < 4; ++mt) {
          const int r = warp_m * 64 + mt * 16 + (lane >> 2);
          const uint2 x00 = A2[r * SP2 + kb];
          const uint2 x10 = A2[(r + 8) * SP2 + kb];
          const uint2 x01 = A2[r * SP2 + kb + 4];
          const uint2 x11 = A2[(r + 8) * SP2 + kb + 4];
          ah[mt][0] = x00.x; ah[mt][1] = x10.x;
          ah[mt][2] = x01.x; ah[mt][3] = x11.x;
          al[mt][0] = x00.y; al[mt][1] = x10.y;
          al[mt][2] = x01.y; al[mt][3] = x11.y;
        }
        uint32_t bh[4][2], bl[4][2];
#pragma unroll
        for (int nt = 0; nt < 4; ++nt) {
          const int n = warp_n * 32 + nt * 8 + (lane >> 2);
          const uint2 y0 = B2[n * SP2 + kb];
          const uint2 y1 = B2[n * SP2 + kb + 4];
          bh[nt][0] = y0.x; bh[nt][1] = y1.x;
          bl[nt][0] = y0.y; bl[nt][1] = y1.y;
        }
#pragma unroll
        for (int mt = 0; mt < 4; ++mt)
#pragma unroll
          for (int nt = 0; nt < 4; ++nt) {
            mma_tf32(acc[mt][nt], ah[mt], bh[nt]);
            mma_tf32(acc[mt][nt], ah[mt], bl[nt]);
            mma_tf32(acc[mt][nt], al[mt], bh[nt]);
          }
      }
    }

    // split+store chunk c+1 into the other buffer (its readers are done)
    if (more) {
      uint2* A2 = gsm + ((c + 1) & 1) * (2 * TILE_U2);
      uint2* B2 = A2 + TILE_U2;
      SPLIT_STORE4(A2, sa0, pa0);
      SPLIT_STORE4(A2, sa1, pa1);
      SPLIT_STORE4(B2, sa0, pb0);
      SPLIT_STORE4(B2, sa1, pb1);
    }
  }

#pragma unroll
  for (int mt = 0; mt < 4; ++mt) {
#pragma unroll
    for (int nt = 0; nt < 4; ++nt) {
      const int r = m0 + warp_m * 64 + mt * 16 + (lane >> 2);
      const int n = n0 + warp_n * 32 + nt * 8 + (lane & 3) * 2;
      const float b0 = bias[n], b1 = bias[n + 1];
      float2 v0 = {acc[mt][nt][0] + b0, acc[mt][nt][1] + b1};
      float2 v1 = {acc[mt][nt][2] + b0, acc[mt][nt][3] + b1};
      if (MODE == 0) {
        const int which = n >> 10;
        float* dstv = (which == 0) ? g_q : (which == 1) ? g_k : g_v;
        const int rem = n & 1023;
        const int h = rem >> 6;
        const int d = rem & 63;
        const int b_ = r >> 11, s_ = r & 2047;
        float* base = dstv + (size_t)(((b_ << 4) + h) * SEQ) * HD + d;
        *(float2*)(base + (size_t)s_ * HD) = v0;
        *(float2*)(base + (size_t)(s_ + 8) * HD) = v1;
      } else {
        *(float2*)(out + (size_t)r * EMB + n) = v0;
        *(float2*)(out + (size_t)(r + 8) * EMB + n) = v1;
      }
    }
  }
}

// ---------------------------------------------------------------------------
// Flash attention v3 (UNCHANGED from R7 — known good):
// plain tf32 mma, CTA = 128 q-rows, 256 threads / 8 warps, KV tiles of 32,
// K2/V2 double-buffered (one sync per tile), K/V prefetched to registers.
// Q pre-scaled by 1/sqrt(EMB)=1/32.
// ---------------------------------------------------------------------------
#define AT_K2_OFF 0
#define AT_V2_OFF (2 * 9216)
#define AT_P2_OFF (2 * 9216 + 2 * 10240)
#define ATTN_SMEM_BYTES (AT_P2_OFF + 128 * 20 * 8)  // 59392

__global__ __launch_bounds__(256, 2) void flash_mma_kernel() {
  extern __shared__ char asm_raw[];
  float (*Qs)[68] = reinterpret_cast<float(*)[68]>(asm_raw);
  uint2 (*P2)[20] = reinterpret_cast<uint2(*)[20]>(asm_raw + AT_P2_OFF);

  const int tid = threadIdx.x;
  const int lane = tid & 31;
  const int w = tid >> 5;
  const int grp = lane >> 2;     // 0..7
  const int qp = lane & 3;       // 0..3
  const int bh = blockIdx.x;     // 0..63
  const int q0 = blockIdx.y * 128;
  const int b = bh >> 4, h = bh & 15;
  const int qrow = w * 16 + grp;
  const float SCALE = 0.03125f;  // 1/sqrt(1024)

  const float* Qg = g_q + (size_t)(bh * SEQ + q0) * HD;
  const float* Kg = g_k + (size_t)bh * SEQ * HD;
  const float* Vg = g_v + (size_t)bh * SEQ * HD;

#pragma unroll
  for (int it = 0; it < 8; ++it) {
    const int slot = it * 256 + tid;
    const int r = slot >> 4;
    const int c = (slot & 15) * 4;
    *(float4*)&Qs[r][c] = *(const float4*)(Qg + r * HD + c);
  }
  __syncthreads();

  uint32_t qf[8][4];
#pragma unroll
  for (int ks = 0; ks < 8; ++ks) {
    qf[ks][0] = f2tf32(Qs[qrow][ks * 8 + qp] * SCALE);
    qf[ks][1] = f2tf32(Qs[qrow + 8][ks * 8 + qp] * SCALE);
    qf[ks][2] = f2tf32(Qs[qrow][ks * 8 + qp + 4] * SCALE);
    qf[ks][3] = f2tf32(Qs[qrow + 8][ks * 8 + qp + 4] * SCALE);
  }

  const int key_a = tid >> 4;
  const int key_b = 16 + key_a;
  const int c4 = (tid & 15) * 4;

  float4 kra = *(const float4*)(Kg + (size_t)key_a * HD + c4);
  float4 krb = *(const float4*)(Kg + (size_t)key_b * HD + c4);
  float4 vra = *(const float4*)(Vg + (size_t)key_a * HD + c4);
  float4 vrb = *(const float4*)(Vg + (size_t)key_b * HD + c4);

  __syncthreads();  // Q fragments extracted -> safe to overwrite Qs union

  float o[8][4] = {};
  float m0v = -1e30f, m1v = -1e30f;
  float l0v = 0.f, l1v = 0.f;

  {
    uint2 (*K2)[36] = reinterpret_cast<uint2(*)[36]>(asm_raw + AT_K2_OFF);
    uint2 (*V2)[20] = reinterpret_cast<uint2(*)[20]>(asm_raw + AT_V2_OFF);
    const float ka0[4] = {kra.x, kra.y, kra.z, kra.w};
    const float kb0[4] = {krb.x, krb.y, krb.z, krb.w};
    const float va0[4] = {vra.x, vra.y, vra.z, vra.w};
    const float vb0[4] = {vrb.x, vrb.y, vrb.z, vrb.w};
    const int kidx_a = (key_a >> 3) * 4 + (key_a & 3);
    const int kcomp_a = (key_a >> 2) & 1;
    const int kidx_b = (key_b >> 3) * 4 + (key_b & 3);
    const int kcomp_b = (key_b >> 2) & 1;
#pragma unroll
    for (int j = 0; j < 4; ++j) {
      const int d = c4 + j;
      const int idx = (d >> 3) * 4 + (d & 3);
      const int comp = (d >> 2) & 1;
      ((uint32_t*)&K2[key_a][idx])[comp] = f2tf32(ka0[j]);
      ((uint32_t*)&K2[key_b][idx])[comp] = f2tf32(kb0[j]);
      ((uint32_t*)&V2[d][kidx_a])[kcomp_a] = f2tf32(va0[j]);
      ((uint32_t*)&V2[d][kidx_b])[kcomp_b] = f2tf32(vb0[j]);
    }
  }

  for (int jt = 0; jt < SEQ / 32; ++jt) {
    __syncthreads();

    const bool more = (jt + 1 < SEQ / 32);
    if (more) {
      const size_t jb = (size_t)(jt + 1) * 32;
      kra = *(const float4*)(Kg + (jb + key_a) * HD + c4);
      krb = *(const float4*)(Kg + (jb + key_b) * HD + c4);
      vra = *(const float4*)(Vg + (jb + key_a) * HD + c4);
      vrb = *(const float4*)(Vg + (jb + key_b) * HD + c4);
    }

    const int cbuf = jt & 1;
    uint2 (*K2)[36] = reinterpret_cast<uint2(*)[36]>(asm_raw + AT_K2_OFF + cbuf * 9216);
    uint2 (*V2)[20] = reinterpret_cast<uint2(*)[20]>(asm_raw + AT_V2_OFF + cbuf * 10240);

    float s[4][4] = {};
#pragma unroll
    for (int nt = 0; nt < 4; ++nt) {
#pragma unroll
      for (int ks = 0; ks < 8; ++ks) {
        const uint2 bv = K2[nt * 8 + grp][ks * 4 + qp];
        uint32_t b2[2] = {bv.x, bv.y};
        mma_tf32(s[nt], qf[ks], b2);
      }
    }

    float mx0 = -1e30f, mx1 = -1e30f;
#pragma unroll
    for (int nt = 0; nt < 4; ++nt) {
      mx0 = fmaxf(mx0, fmaxf(s[nt][0], s[nt][1]));
      mx1 = fmaxf(mx1, fmaxf(s[nt][2], s[nt][3]));
    }
    mx0 = fmaxf(mx0, __shfl_xor_sync(0xffffffffu, mx0, 1));
    mx0 = fmaxf(mx0, __shfl_xor_sync(0xffffffffu, mx0, 2));
    mx1 = fmaxf(mx1, __shfl_xor_sync(0xffffffffu, mx1, 1));
    mx1 = fmaxf(mx1, __shfl_xor_sync(0xffffffffu, mx1, 2));
    const float mn0 = fmaxf(m0v, mx0);
    const float mn1 = fmaxf(m1v, mx1);
    const float c0 = __expf(m0v - mn0);
    const float c1 = __expf(m1v - mn1);
    m0v = mn0; m1v = mn1;

    float ls0 = 0.f, ls1 = 0.f;
    float p[4][4];
#pragma unroll
    for (int nt = 0; nt < 4; ++nt) {
      p[nt][0] = __expf(s[nt][0] - mn0);
      p[nt][1] = __expf(s[nt][1] - mn0);
      p[nt][2] = __expf(s[nt][2] - mn1);
      p[nt][3] = __expf(s[nt][3] - mn1);
      ls0 += p[nt][0] + p[nt][1];
      ls1 += p[nt][2] + p[nt][3];
    }
    ls0 += __shfl_xor_sync(0xffffffffu, ls0, 1);
    ls0 += __shfl_xor_sync(0xffffffffu, ls0, 2);
    ls1 += __shfl_xor_sync(0xffffffffu, ls1, 1);
    ls1 += __shfl_xor_sync(0xffffffffu, ls1, 2);
    l0v = l0v * c0 + ls0;
    l1v = l1v * c1 + ls1;

#pragma unroll
    for (int dt = 0; dt < 8; ++dt) {
      o[dt][0] *= c0; o[dt][1] *= c0;
      o[dt][2] *= c1; o[dt][3] *= c1;
    }

#pragma unroll
    for (int nt = 0; nt < 4; ++nt) {
#pragma unroll
      for (int j = 0; j < 2; ++j) {
        const int col = nt * 8 + qp * 2 + j;
        const int kst = col >> 3;
        const int idx = kst * 4 + (col & 3);
        const int comp = (col >> 2) & 1;
        ((uint32_t*)&P2[qrow][idx])[comp] = f2tf32(p[nt][j]);
        ((uint32_t*)&P2[qrow + 8][idx])[comp] = f2tf32(p[nt][2 + j]);
      }
    }
    __syncwarp();

#pragma unroll
    for (int kst = 0; kst < 4; ++kst) {
      const uint2 pa0 = P2[qrow][kst * 4 + qp];
      const uint2 pa1 = P2[qrow + 8][kst * 4 + qp];
      uint32_t a2[4] = {pa0.x, pa1.x, pa0.y, pa1.y};
#pragma unroll
      for (int dt = 0; dt < 8; ++dt) {
        const uint2 vb = V2[dt * 8 + grp][kst * 4 + qp];
        uint32_t b2[2] = {vb.x, vb.y};
        mma_tf32(o[dt], a2, b2);
      }
    }

    if (more) {
      uint2 (*K2n)[36] = reinterpret_cast<uint2(*)[36]>(asm_raw + AT_K2_OFF + (cbuf ^ 1) * 9216);
      uint2 (*V2n)[20] = reinterpret_cast<uint2(*)[20]>(asm_raw + AT_V2_OFF + (cbuf ^ 1) * 10240);
      const float ka0[4] = {kra.x, kra.y, kra.z, kra.w};
      const float kb0[4] = {krb.x, krb.y, krb.z, krb.w};
      const float va0[4] = {vra.x, vra.y, vra.z, vra.w};
      const float vb0[4] = {vrb.x, vrb.y, vrb.z, vrb.w};
      const int kidx_a = (key_a >> 3) * 4 + (key_a & 3);
      const int kcomp_a = (key_a >> 2) & 1;
      const int kidx_b = (key_b >> 3) * 4 + (key_b & 3);
      const int kcomp_b = (key_b >> 2) & 1;
#pragma unroll
      for (int j = 0; j < 4; ++j) {
        const int d = c4 + j;
        const int idx = (d >> 3) * 4 + (d & 3);
        const int comp = (d >> 2) & 1;
        ((uint32_t*)&K2n[key_a][idx])[comp] = f2tf32(ka0[j]);
        ((uint32_t*)&K2n[key_b][idx])[comp] = f2tf32(kb0[j]);
        ((uint32_t*)&V2n[d][kidx_a])[kcomp_a] = f2tf32(va0[j]);
        ((uint32_t*)&V2n[d][kidx_b])[kcomp_b] = f2tf32(vb0[j]);
      }
    }
  }

  const float il0 = 1.f / l0v;
  const float il1 = 1.f / l1v;
  float* aob = g_ao + ((size_t)(b * SEQ + q0)) * EMB + h * HD;
#pragma unroll
  for (int dt = 0; dt < 8; ++dt) {
    const int d0 = dt * 8 + qp * 2;
    float2 v0 = {o[dt][0] * il0, o[dt][1] * il0};
    float2 v1 = {o[dt][2] * il1, o[dt][3] * il1};
    *(float2*)(aob + (size_t)qrow * EMB + d0) = v0;
    *(float2*)(aob + (size_t)(qrow + 8) * EMB + d0) = v1;
  }
}

// ---------------------------------------------------------------------------
extern "C" void kernel_launch(void* const* d_in, const int* in_sizes, int n_in,
                              void* d_out, int out_size) {
  (void)in_sizes; (void)n_in; (void)out_size;
  const float* query = (const float*)d_in[0];
  // d_in[1]=key, d_in[2]=value: ignored by the reference module
  const float* Wqkv = (const float*)d_in[3];
  const float* bqkv = (const float*)d_in[4];
  const float* Wout = (const float*)d_in[5];
  const float* bout = (const float*)d_in[6];
  float* out = (float*)d_out;

  cudaFuncSetAttribute(gemm_mma_kernel<0>,
                       cudaFuncAttributeMaxDynamicSharedMemorySize,
                       GEMM_SMEM_BYTES);
  cudaFuncSetAttribute(gemm_mma_kernel<1>,
                       cudaFuncAttributeMaxDynamicSharedMemorySize,
                       GEMM_SMEM_BYTES);
  cudaFuncSetAttribute(flash_mma_kernel,
                       cudaFuncAttributeMaxDynamicSharedMemorySize,
                       ATTN_SMEM_BYTES);

  dim3 g1(24, 64);   // 3072/128 x 8192/128
  gemm_mma_kernel<0><<<g1, 256, GEMM_SMEM_BYTES>>>(query, Wqkv, bqkv, nullptr);

  dim3 g2(64, 16);   // (b*h) x (S/128)
  flash_mma_kernel<<<g2, 256, ATTN_SMEM_BYTES>>>();

  dim3 g3(8, 64);    // 1024/128 x 8192/128
  gemm_mma_kernel<1><<<g3, 256, GEMM_SMEM_BYTES>>>(nullptr, Wout, bout, out);
}

// round 10
// speedup vs baseline: 1.8016x; 1.8016x over previous
#include <cuda_runtime.h>
#include <cstdint>

#define BB 4
#define SEQ 2048
#define EMB 1024
#define NH 16
#define HD 64
#define MT (BB * SEQ)  // 8192 tokens

// Scratch (allocation-free rule: device globals)
__device__ float g_q[BB * NH * SEQ * HD];   // [b][h][s][d]
__device__ float g_k[BB * NH * SEQ * HD];
__device__ float g_v[BB * NH * SEQ * HD];
__device__ float g_ao[MT * EMB];            // attention out, [b][s][h*64+d] == [m][e]

// ---------------------------------------------------------------------------
// tf32 helpers (baseline PTX, works at .target sm_100)
// ---------------------------------------------------------------------------
__device__ __forceinline__ uint32_t f2tf32(float x) {
  uint32_t r;
  asm("cvt.rna.tf32.f32 %0, %1;" : "=r"(r) : "f"(x));
  return r;
}

__device__ __forceinline__ void split1(float v, uint32_t& h, uint32_t& l) {
  h = f2tf32(v);
  l = f2tf32(v - __uint_as_float(h));
}

__device__ __forceinline__ float ex2(float x) {
  float r;
  asm("ex2.approx.f32 %0, %1;" : "=f"(r) : "f"(x));
  return r;
}

__device__ __forceinline__ void mma_tf32(float* c, const uint32_t* a,
                                         const uint32_t* b) {
  asm volatile(
      "mma.sync.aligned.m16n8k8.row.col.f32.tf32.tf32.f32 "
      "{%0,%1,%2,%3}, {%4,%5,%6,%7}, {%8,%9}, {%0,%1,%2,%3};"
      : "+f"(c[0]), "+f"(c[1]), "+f"(c[2]), "+f"(c[3])
      : "r"(a[0]), "r"(a[1]), "r"(a[2]), "r"(a[3]), "r"(b[0]), "r"(b[1]));
}

// ---------------------------------------------------------------------------
// tf32 split GEMM (R7 structure — separate hi/lo arrays, LDS.32 frags,
// double-buffered, ONE sync per BK=16 chunk), now with A split 2-term:
//   D ≈ (A_hi + A_lo) · B_hi      (B kept tf32-hi only; err ~1.2e-4 rel)
// CTA 128x128, 256 threads (8 warps, each 64x32 out). No reg cap (R8/R9
// proved capping/interleaving -> spills).
// MODE 0: A=query, scatter into g_q/g_k/g_v. MODE 1: A=g_ao, write out.
// ---------------------------------------------------------------------------
#define SPAD 20                 // row stride in words (conflict-free frags)
#define BUFW (128 * SPAD)       // one tile in words
#define GEMM_SMEM_BYTES (2 * 3 * BUFW * 4)  // 2 bufs x {AH,AL,BH} = 61440 B

template <int MODE>
__global__ __launch_bounds__(256) void gemm_mma_kernel(
    const float* __restrict__ A, const float* __restrict__ B,
    const float* __restrict__ bias, float* __restrict__ out) {
  extern __shared__ uint32_t gsm[];

  const int tid = threadIdx.x;
  const int lane = tid & 31;
  const int wid = tid >> 5;
  const int warp_m = wid & 1;        // 2 warps over M
  const int warp_n = wid >> 1;       // 4 warps over N
  const int m0 = blockIdx.y * 128;
  const int n0 = blockIdx.x * 128;

  const float* Asrc = (MODE == 0) ? A : g_ao;

  const int ldr = tid >> 2;          // rows 0..63 (+64 for second half)
  const int ldc = (tid & 3) * 4;     // 0,4,8,12

  const float* Ap0 = Asrc + (size_t)(m0 + ldr) * EMB + ldc;
  const float* Ap1 = Asrc + (size_t)(m0 + 64 + ldr) * EMB + ldc;
  const float* Bp0 = B + (size_t)(n0 + ldr) * EMB + ldc;
  const float* Bp1 = B + (size_t)(n0 + 64 + ldr) * EMB + ldc;

  float acc[4][4][4] = {};  // [mt][nt][reg]

  const int s0 = ldr * SPAD + ldc;
  const int s1 = (ldr + 64) * SPAD + ldc;

  float4 pa0 = *(const float4*)(Ap0);
  float4 pa1 = *(const float4*)(Ap1);
  float4 pb0 = *(const float4*)(Bp0);
  float4 pb1 = *(const float4*)(Bp1);

  // store helpers: A split hi/lo, B hi only
#define A_SPLIT_STORE(AH, AL, idx, v)                               \
  do {                                                              \
    uint4 h, l;                                                     \
    split1((v).x, h.x, l.x); split1((v).y, h.y, l.y);               \
    split1((v).z, h.z, l.z); split1((v).w, h.w, l.w);               \
    *(uint4*)&(AH)[idx] = h;                                        \
    *(uint4*)&(AL)[idx] = l;                                        \
  } while (0)
#define B_HI_STORE(BH, idx, v)                                      \
  do {                                                              \
    uint4 h;                                                        \
    h.x = f2tf32((v).x); h.y = f2tf32((v).y);                       \
    h.z = f2tf32((v).z); h.w = f2tf32((v).w);                       \
    *(uint4*)&(BH)[idx] = h;                                        \
  } while (0)

  // prologue: chunk 0 -> buffer 0
  {
    uint32_t* AH = gsm;
    uint32_t* AL = gsm + BUFW;
    uint32_t* BH = gsm + 2 * BUFW;
    A_SPLIT_STORE(AH, AL, s0, pa0);
    A_SPLIT_STORE(AH, AL, s1, pa1);
    B_HI_STORE(BH, s0, pb0);
    B_HI_STORE(BH, s1, pb1);
  }

  for (int c = 0; c < EMB / 16; ++c) {
    __syncthreads();  // stores of chunk c done; computes of chunk c-1 done

    const bool more = (c + 1 < EMB / 16);
    if (more) {
      const int off = (c + 1) * 16;
      pa0 = *(const float4*)(Ap0 + off);
      pa1 = *(const float4*)(Ap1 + off);
      pb0 = *(const float4*)(Bp0 + off);
      pb1 = *(const float4*)(Bp1 + off);
    }

    // compute chunk c from buffer c&1
    {
      const uint32_t* cb = gsm + (c & 1) * (3 * BUFW);
      const uint32_t* s_ahi = cb;
      const uint32_t* s_alo = cb + BUFW;
      const uint32_t* s_bhi = cb + 2 * BUFW;
#pragma unroll
      for (int kc = 0; kc < 2; ++kc) {
        const int kb = kc * 8 + (lane & 3);
        uint32_t ah[4][4], al[4][4];
#pragma unroll
        for (int mt = 0; mt < 4; ++mt) {
          const int r = warp_m * 64 + mt * 16 + (lane >> 2);
          const int i0 = r * SPAD + kb;
          const int i1 = (r + 8) * SPAD + kb;
          ah[mt][0] = s_ahi[i0];     ah[mt][1] = s_ahi[i1];
          ah[mt][2] = s_ahi[i0 + 4]; ah[mt][3] = s_ahi[i1 + 4];
          al[mt][0] = s_alo[i0];     al[mt][1] = s_alo[i1];
          al[mt][2] = s_alo[i0 + 4]; al[mt][3] = s_alo[i1 + 4];
        }
        uint32_t bh[4][2];
#pragma unroll
        for (int nt = 0; nt < 4; ++nt) {
          const int n = warp_n * 32 + nt * 8 + (lane >> 2);
          const int i0 = n * SPAD + kb;
          bh[nt][0] = s_bhi[i0]; bh[nt][1] = s_bhi[i0 + 4];
        }
#pragma unroll
        for (int mt = 0; mt < 4; ++mt)
#pragma unroll
          for (int nt = 0; nt < 4; ++nt) {
            mma_tf32(acc[mt][nt], ah[mt], bh[nt]);
            mma_tf32(acc[mt][nt], al[mt], bh[nt]);
          }
      }
    }

    // split+store chunk c+1 into the other buffer (its readers are done)
    if (more) {
      uint32_t* nb = gsm + ((c + 1) & 1) * (3 * BUFW);
      uint32_t* AH = nb;
      uint32_t* AL = nb + BUFW;
      uint32_t* BH = nb + 2 * BUFW;
      A_SPLIT_STORE(AH, AL, s0, pa0);
      A_SPLIT_STORE(AH, AL, s1, pa1);
      B_HI_STORE(BH, s0, pb0);
      B_HI_STORE(BH, s1, pb1);
    }
  }

#pragma unroll
  for (int mt = 0; mt < 4; ++mt) {
#pragma unroll
    for (int nt = 0; nt < 4; ++nt) {
      const int r = m0 + warp_m * 64 + mt * 16 + (lane >> 2);
      const int n = n0 + warp_n * 32 + nt * 8 + (lane & 3) * 2;
      const float b0 = bias[n], b1 = bias[n + 1];
      float2 v0 = {acc[mt][nt][0] + b0, acc[mt][nt][1] + b1};
      float2 v1 = {acc[mt][nt][2] + b0, acc[mt][nt][3] + b1};
      if (MODE == 0) {
        const int which = n >> 10;
        float* dstv = (which == 0) ? g_q : (which == 1) ? g_k : g_v;
        const int rem = n & 1023;
        const int h = rem >> 6;
        const int d = rem & 63;
        const int b_ = r >> 11, s_ = r & 2047;
        float* base = dstv + (size_t)(((b_ << 4) + h) * SEQ) * HD + d;
        *(float2*)(base + (size_t)s_ * HD) = v0;
        *(float2*)(base + (size_t)(s_ + 8) * HD) = v1;
      } else {
        *(float2*)(out + (size_t)r * EMB + n) = v0;
        *(float2*)(out + (size_t)(r + 8) * EMB + n) = v1;
      }
    }
  }
}

// ---------------------------------------------------------------------------
// Flash attention v3 (R7 structure — known good), one change: softmax in
// base-2 domain (log2e folded into Q pre-scale; ex2.approx replaces __expf).
// plain tf32 mma, CTA = 128 q-rows, 256 threads / 8 warps, KV tiles of 32,
// K2/V2 double-buffered (one sync per tile), K/V prefetched to registers.
// ---------------------------------------------------------------------------
#define AT_K2_OFF 0
#define AT_V2_OFF (2 * 9216)
#define AT_P2_OFF (2 * 9216 + 2 * 10240)
#define ATTN_SMEM_BYTES (AT_P2_OFF + 128 * 20 * 8)  // 59392

__global__ __launch_bounds__(256, 2) void flash_mma_kernel() {
  extern __shared__ char asm_raw[];
  float (*Qs)[68] = reinterpret_cast<float(*)[68]>(asm_raw);
  uint2 (*P2)[20] = reinterpret_cast<uint2(*)[20]>(asm_raw + AT_P2_OFF);

  const int tid = threadIdx.x;
  const int lane = tid & 31;
  const int w = tid >> 5;
  const int grp = lane >> 2;     // 0..7
  const int qp = lane & 3;       // 0..3
  const int bh = blockIdx.x;     // 0..63
  const int q0 = blockIdx.y * 128;
  const int b = bh >> 4, h = bh & 15;
  const int qrow = w * 16 + grp;
  const float SCALE2 = 0.03125f * 1.44269504089f;  // log2e / sqrt(1024)

  const float* Qg = g_q + (size_t)(bh * SEQ + q0) * HD;
  const float* Kg = g_k + (size_t)bh * SEQ * HD;
  const float* Vg = g_v + (size_t)bh * SEQ * HD;

#pragma unroll
  for (int it = 0; it < 8; ++it) {
    const int slot = it * 256 + tid;
    const int r = slot >> 4;
    const int c = (slot & 15) * 4;
    *(float4*)&Qs[r][c] = *(const float4*)(Qg + r * HD + c);
  }
  __syncthreads();

  uint32_t qf[8][4];
#pragma unroll
  for (int ks = 0; ks < 8; ++ks) {
    qf[ks][0] = f2tf32(Qs[qrow][ks * 8 + qp] * SCALE2);
    qf[ks][1] = f2tf32(Qs[qrow + 8][ks * 8 + qp] * SCALE2);
    qf[ks][2] = f2tf32(Qs[qrow][ks * 8 + qp + 4] * SCALE2);
    qf[ks][3] = f2tf32(Qs[qrow + 8][ks * 8 + qp + 4] * SCALE2);
  }

  const int key_a = tid >> 4;
  const int key_b = 16 + key_a;
  const int c4 = (tid & 15) * 4;

  float4 kra = *(const float4*)(Kg + (size_t)key_a * HD + c4);
  float4 krb = *(const float4*)(Kg + (size_t)key_b * HD + c4);
  float4 vra = *(const float4*)(Vg + (size_t)key_a * HD + c4);
  float4 vrb = *(const float4*)(Vg + (size_t)key_b * HD + c4);

  __syncthreads();  // Q fragments extracted -> safe to overwrite Qs union

  float o[8][4] = {};
  float m0v = -1e30f, m1v = -1e30f;   // base-2 domain
  float l0v = 0.f, l1v = 0.f;

  {
    uint2 (*K2)[36] = reinterpret_cast<uint2(*)[36]>(asm_raw + AT_K2_OFF);
    uint2 (*V2)[20] = reinterpret_cast<uint2(*)[20]>(asm_raw + AT_V2_OFF);
    const float ka0[4] = {kra.x, kra.y, kra.z, kra.w};
    const float kb0[4] = {krb.x, krb.y, krb.z, krb.w};
    const float va0[4] = {vra.x, vra.y, vra.z, vra.w};
    const float vb0[4] = {vrb.x, vrb.y, vrb.z, vrb.w};
    const int kidx_a = (key_a >> 3) * 4 + (key_a & 3);
    const int kcomp_a = (key_a >> 2) & 1;
    const int kidx_b = (key_b >> 3) * 4 + (key_b & 3);
    const int kcomp_b = (key_b >> 2) & 1;
#pragma unroll
    for (int j = 0; j < 4; ++j) {
      const int d = c4 + j;
      const int idx = (d >> 3) * 4 + (d & 3);
      const int comp = (d >> 2) & 1;
      ((uint32_t*)&K2[key_a][idx])[comp] = f2tf32(ka0[j]);
      ((uint32_t*)&K2[key_b][idx])[comp] = f2tf32(kb0[j]);
      ((uint32_t*)&V2[d][kidx_a])[kcomp_a] = f2tf32(va0[j]);
      ((uint32_t*)&V2[d][kidx_b])[kcomp_b] = f2tf32(vb0[j]);
    }
  }

  for (int jt = 0; jt < SEQ / 32; ++jt) {
    __syncthreads();

    const bool more = (jt + 1 < SEQ / 32);
    if (more) {
      const size_t jb = (size_t)(jt + 1) * 32;
      kra = *(const float4*)(Kg + (jb + key_a) * HD + c4);
      krb = *(const float4*)(Kg + (jb + key_b) * HD + c4);
      vra = *(const float4*)(Vg + (jb + key_a) * HD + c4);
      vrb = *(const float4*)(Vg + (jb + key_b) * HD + c4);
    }

    const int cbuf = jt & 1;
    uint2 (*K2)[36] = reinterpret_cast<uint2(*)[36]>(asm_raw + AT_K2_OFF + cbuf * 9216);
    uint2 (*V2)[20] = reinterpret_cast<uint2(*)[20]>(asm_raw + AT_V2_OFF + cbuf * 10240);

    float s[4][4] = {};
#pragma unroll
    for (int nt = 0; nt < 4; ++nt) {
#pragma unroll
      for (int ks = 0; ks < 8; ++ks) {
        const uint2 bv = K2[nt * 8 + grp][ks * 4 + qp];
        uint32_t b2[2] = {bv.x, bv.y};
        mma_tf32(s[nt], qf[ks], b2);
      }
    }

    float mx0 = -1e30f, mx1 = -1e30f;
#pragma unroll
    for (int nt = 0; nt < 4; ++nt) {
      mx0 = fmaxf(mx0, fmaxf(s[nt][0], s[nt][1]));
      mx1 = fmaxf(mx1, fmaxf(s[nt][2], s[nt][3]));
    }
    mx0 = fmaxf(mx0, __shfl_xor_sync(0xffffffffu, mx0, 1));
    mx0 = fmaxf(mx0, __shfl_xor_sync(0xffffffffu, mx0, 2));
    mx1 = fmaxf(mx1, __shfl_xor_sync(0xffffffffu, mx1, 1));
    mx1 = fmaxf(mx1, __shfl_xor_sync(0xffffffffu, mx1, 2));
    const float mn0 = fmaxf(m0v, mx0);
    const float mn1 = fmaxf(m1v, mx1);
    const float c0 = ex2(m0v - mn0);
    const float c1 = ex2(m1v - mn1);
    m0v = mn0; m1v = mn1;

    float ls0 = 0.f, ls1 = 0.f;
    float p[4][4];
#pragma unroll
    for (int nt = 0; nt < 4; ++nt) {
      p[nt][0] = ex2(s[nt][0] - mn0);
      p[nt][1] = ex2(s[nt][1] - mn0);
      p[nt][2] = ex2(s[nt][2] - mn1);
      p[nt][3] = ex2(s[nt][3] - mn1);
      ls0 += p[nt][0] + p[nt][1];
      ls1 += p[nt][2] + p[nt][3];
    }
    ls0 += __shfl_xor_sync(0xffffffffu, ls0, 1);
    ls0 += __shfl_xor_sync(0xffffffffu, ls0, 2);
    ls1 += __shfl_xor_sync(0xffffffffu, ls1, 1);
    ls1 += __shfl_xor_sync(0xffffffffu, ls1, 2);
    l0v = l0v * c0 + ls0;
    l1v = l1v * c1 + ls1;

#pragma unroll
    for (int dt = 0; dt < 8; ++dt) {
      o[dt][0] *= c0; o[dt][1] *= c0;
      o[dt][2] *= c1; o[dt][3] *= c1;
    }

#pragma unroll
    for (int nt = 0; nt < 4; ++nt) {
#pragma unroll
      for (int j = 0; j < 2; ++j) {
        const int col = nt * 8 + qp * 2 + j;
        const int kst = col >> 3;
        const int idx = kst * 4 + (col & 3);
        const int comp = (col >> 2) & 1;
        ((uint32_t*)&P2[qrow][idx])[comp] = f2tf32(p[nt][j]);
        ((uint32_t*)&P2[qrow + 8][idx])[comp] = f2tf32(p[nt][2 + j]);
      }
    }
    __syncwarp();

#pragma unroll
    for (int kst = 0; kst < 4; ++kst) {
      const uint2 pa0 = P2[qrow][kst * 4 + qp];
      const uint2 pa1 = P2[qrow + 8][kst * 4 + qp];
      uint32_t a2[4] = {pa0.x, pa1.x, pa0.y, pa1.y};
#pragma unroll
      for (int dt = 0; dt < 8; ++dt) {
        const uint2 vb = V2[dt * 8 + grp][kst * 4 + qp];
        uint32_t b2[2] = {vb.x, vb.y};
        mma_tf32(o[dt], a2, b2);
      }
    }

    if (more) {
      uint2 (*K2n)[36] = reinterpret_cast<uint2(*)[36]>(asm_raw + AT_K2_OFF + (cbuf ^ 1) * 9216);
      uint2 (*V2n)[20] = reinterpret_cast<uint2(*)[20]>(asm_raw + AT_V2_OFF + (cbuf ^ 1) * 10240);
      const float ka0[4] = {kra.x, kra.y, kra.z, kra.w};
      const float kb0[4] = {krb.x, krb.y, krb.z, krb.w};
      const float va0[4] = {vra.x, vra.y, vra.z, vra.w};
      const float vb0[4] = {vrb.x, vrb.y, vrb.z, vrb.w};
      const int kidx_a = (key_a >> 3) * 4 + (key_a & 3);
      const int kcomp_a = (key_a >> 2) & 1;
      const int kidx_b = (key_b >> 3) * 4 + (key_b & 3);
      const int kcomp_b = (key_b >> 2) & 1;
#pragma unroll
      for (int j = 0; j < 4; ++j) {
        const int d = c4 + j;
        const int idx = (d >> 3) * 4 + (d & 3);
        const int comp = (d >> 2) & 1;
        ((uint32_t*)&K2n[key_a][idx])[comp] = f2tf32(ka0[j]);
        ((uint32_t*)&K2n[key_b][idx])[comp] = f2tf32(kb0[j]);
        ((uint32_t*)&V2n[d][kidx_a])[kcomp_a] = f2tf32(va0[j]);
        ((uint32_t*)&V2n[d][kidx_b])[kcomp_b] = f2tf32(vb0[j]);
      }
    }
  }

  const float il0 = 1.f / l0v;
  const float il1 = 1.f / l1v;
  float* aob = g_ao + ((size_t)(b * SEQ + q0)) * EMB + h * HD;
#pragma unroll
  for (int dt = 0; dt < 8; ++dt) {
    const int d0 = dt * 8 + qp * 2;
    float2 v0 = {o[dt][0] * il0, o[dt][1] * il0};
    float2 v1 = {o[dt][2] * il1, o[dt][3] * il1};
    *(float2*)(aob + (size_t)qrow * EMB + d0) = v0;
    *(float2*)(aob + (size_t)(qrow + 8) * EMB + d0) = v1;
  }
}

// ---------------------------------------------------------------------------
extern "C" void kernel_launch(void* const* d_in, const int* in_sizes, int n_in,
                              void* d_out, int out_size) {
  (void)in_sizes; (void)n_in; (void)out_size;
  const float* query = (const float*)d_in[0];
  // d_in[1]=key, d_in[2]=value: ignored by the reference module
  const float* Wqkv = (const float*)d_in[3];
  const float* bqkv = (const float*)d_in[4];
  const float* Wout = (const float*)d_in[5];
  const float* bout = (const float*)d_in[6];
  float* out = (float*)d_out;

  cudaFuncSetAttribute(gemm_mma_kernel<0>,
                       cudaFuncAttributeMaxDynamicSharedMemorySize,
                       GEMM_SMEM_BYTES);
  cudaFuncSetAttribute(gemm_mma_kernel<1>,
                       cudaFuncAttributeMaxDynamicSharedMemorySize,
                       GEMM_SMEM_BYTES);
  cudaFuncSetAttribute(flash_mma_kernel,
                       cudaFuncAttributeMaxDynamicSharedMemorySize,
                       ATTN_SMEM_BYTES);

  dim3 g1(24, 64);   // 3072/128 x 8192/128
  gemm_mma_kernel<0><<<g1, 256, GEMM_SMEM_BYTES>>>(query, Wqkv, bqkv, nullptr);

  dim3 g2(64, 16);   // (b*h) x (S/128)
  flash_mma_kernel<<<g2, 256, ATTN_SMEM_BYTES>>>();

  dim3 g3(8, 64);    // 1024/128 x 8192/128
  gemm_mma_kernel<1><<<g3, 256, GEMM_SMEM_BYTES>>>(nullptr, Wout, bout, out);
}